// round 6
// baseline (speedup 1.0000x reference)
#include <cuda_runtime.h>

// ---------------------------------------------------------------------------
// Problem constants
// ---------------------------------------------------------------------------
#define BATCH 1024
#define DIN   512
#define DH    1024
#define DOUT  512
#define MHIST 6
#define MAXIT 40
#define LAM   1e-4f

#define SZ (BATCH * DH)   // one history slot: 1024 x 1024 floats

// ---------------------------------------------------------------------------
// Scratch (device globals: no runtime allocation allowed)
// Layout: slot-major, each slot is a contiguous [1024 x 1024] row-major matrix
// ---------------------------------------------------------------------------
__device__ float g_X[MHIST * SZ];     // 24 MB
__device__ float g_F[MHIST * SZ];     // 24 MB
__device__ float g_h[SZ];             // hidden activations
__device__ float g_z[SZ];             // current iterate xk
__device__ float g_alpha[BATCH * MHIST];

// ---------------------------------------------------------------------------
// FP32 GEMM:  C[M,N] = A[M,K] @ B[K,N] + bias  (optional relu, optional dup-store)
// Tiles: BM=128, BN=64, BK=16, thread tile 8x4, 256 threads.
// Inner loop uses packed fma.rn.f32x2 (FFMA2) for 2 MACs/instr.
// All dims are multiples of tile sizes for this problem (no bounds checks).
// ---------------------------------------------------------------------------
template <bool RELU>
__global__ void __launch_bounds__(256, 2)
gemm_kernel(const float* __restrict__ A, const float* __restrict__ B,
            const float* __restrict__ bias, float* __restrict__ C,
            float* __restrict__ C2, int N, int K)
{
    constexpr int BM = 128, BN = 64, BK = 16, TM = 8, TN = 4;
    __shared__ float As[BK][BM + 4];   // +4 pad keeps 16B alignment, reduces STS conflicts
    __shared__ float Bs[BK][BN];

    const int tid = threadIdx.x;
    const int tx  = tid & 15;          // N direction: 16 * TN = 64
    const int ty  = tid >> 4;          // M direction: 16 * TM = 128
    const int m0  = blockIdx.y * BM;
    const int n0  = blockIdx.x * BN;

    // A loader mapping: 512 float4 loads (128 rows x 4 k-chunks), 2 per thread
    const int a_m0 = tid >> 2;             // 0..63
    const int a_m1 = a_m0 + 64;            // 64..127
    const int a_k4 = (tid & 3) * 4;        // 0,4,8,12
    // B loader mapping: 256 float4 loads (16 rows x 16 n-chunks), 1 per thread
    const int b_kk = tid >> 4;              // 0..15
    const int b_n  = (tid & 15) * 4;        // 0..60

    unsigned long long acc[TM][2];
#pragma unroll
    for (int i = 0; i < TM; ++i) { acc[i][0] = 0ull; acc[i][1] = 0ull; }

    // ---- load tile 0 into smem ----
    {
        float4 v0 = *reinterpret_cast<const float4*>(A + (size_t)(m0 + a_m0) * K + a_k4);
        float4 v1 = *reinterpret_cast<const float4*>(A + (size_t)(m0 + a_m1) * K + a_k4);
        As[a_k4 + 0][a_m0] = v0.x; As[a_k4 + 1][a_m0] = v0.y;
        As[a_k4 + 2][a_m0] = v0.z; As[a_k4 + 3][a_m0] = v0.w;
        As[a_k4 + 0][a_m1] = v1.x; As[a_k4 + 1][a_m1] = v1.y;
        As[a_k4 + 2][a_m1] = v1.z; As[a_k4 + 3][a_m1] = v1.w;
        float4 vb = *reinterpret_cast<const float4*>(B + (size_t)b_kk * N + n0 + b_n);
        *reinterpret_cast<float4*>(&Bs[b_kk][b_n]) = vb;
    }
    __syncthreads();

    const int ntiles = K / BK;
    for (int t = 0; t < ntiles; ++t) {
        float4 pa0, pa1, pb;
        const bool has_next = (t + 1 < ntiles);
        if (has_next) {
            const int k0 = (t + 1) * BK;
            pa0 = *reinterpret_cast<const float4*>(A + (size_t)(m0 + a_m0) * K + k0 + a_k4);
            pa1 = *reinterpret_cast<const float4*>(A + (size_t)(m0 + a_m1) * K + k0 + a_k4);
            pb  = *reinterpret_cast<const float4*>(B + (size_t)(k0 + b_kk) * N + n0 + b_n);
        }

#pragma unroll
        for (int kk = 0; kk < BK; ++kk) {
            float4 a0 = *reinterpret_cast<const float4*>(&As[kk][ty * TM]);
            float4 a1 = *reinterpret_cast<const float4*>(&As[kk][ty * TM + 4]);
            ulonglong2 bb = *reinterpret_cast<const ulonglong2*>(&Bs[kk][tx * TN]);
            float av[8] = {a0.x, a0.y, a0.z, a0.w, a1.x, a1.y, a1.z, a1.w};
#pragma unroll
            for (int i = 0; i < 8; ++i) {
                unsigned int ai = __float_as_uint(av[i]);
                unsigned long long a2;
                asm("mov.b64 %0, {%1, %2};" : "=l"(a2) : "r"(ai), "r"(ai));
                asm("fma.rn.f32x2 %0, %1, %2, %3;"
                    : "=l"(acc[i][0]) : "l"(a2), "l"(bb.x), "l"(acc[i][0]));
                asm("fma.rn.f32x2 %0, %1, %2, %3;"
                    : "=l"(acc[i][1]) : "l"(a2), "l"(bb.y), "l"(acc[i][1]));
            }
        }
        __syncthreads();
        if (has_next) {
            As[a_k4 + 0][a_m0] = pa0.x; As[a_k4 + 1][a_m0] = pa0.y;
            As[a_k4 + 2][a_m0] = pa0.z; As[a_k4 + 3][a_m0] = pa0.w;
            As[a_k4 + 0][a_m1] = pa1.x; As[a_k4 + 1][a_m1] = pa1.y;
            As[a_k4 + 2][a_m1] = pa1.z; As[a_k4 + 3][a_m1] = pa1.w;
            *reinterpret_cast<float4*>(&Bs[b_kk][b_n]) = pb;
            __syncthreads();
        }
    }

    // ---- epilogue: bias (+relu), vectorized store ----
    float4 bs4 = *reinterpret_cast<const float4*>(bias + n0 + tx * TN);
#pragma unroll
    for (int i = 0; i < TM; ++i) {
        unsigned int l0, h0, l1, h1;
        asm("mov.b64 {%0, %1}, %2;" : "=r"(l0), "=r"(h0) : "l"(acc[i][0]));
        asm("mov.b64 {%0, %1}, %2;" : "=r"(l1), "=r"(h1) : "l"(acc[i][1]));
        float4 v;
        v.x = __uint_as_float(l0) + bs4.x;
        v.y = __uint_as_float(h0) + bs4.y;
        v.z = __uint_as_float(l1) + bs4.z;
        v.w = __uint_as_float(h1) + bs4.w;
        if (RELU) {
            v.x = fmaxf(v.x, 0.f); v.y = fmaxf(v.y, 0.f);
            v.z = fmaxf(v.z, 0.f); v.w = fmaxf(v.w, 0.f);
        }
        const size_t off = (size_t)(m0 + ty * TM + i) * N + n0 + tx * TN;
        *reinterpret_cast<float4*>(C + off) = v;
        if (C2) *reinterpret_cast<float4*>(C2 + off) = v;
    }
}

// ---------------------------------------------------------------------------
// Anderson alpha: one CTA per batch row.
// Builds G = F - X for the NV valid slots, computes the NVxNV Gram matrix,
// solves the bordered (NV+1)x(NV+1) system [[0,1^T],[1, GG+lam I]] a = e0
// with partial pivoting (matches jnp.linalg.solve incl. the masked-identity
// rows, whose alphas are exactly 0), writes alpha[row][0..5].
// ---------------------------------------------------------------------------
template <int NV>
__global__ void __launch_bounds__(256)
anderson_kernel()
{
    constexpr int NP = NV * (NV + 1) / 2;
    const int row = blockIdx.x;
    const int tid = threadIdx.x;

    const float* xb = g_X + (size_t)row * DH;
    const float* fb = g_F + (size_t)row * DH;

    float s[NP];
#pragma unroll
    for (int p = 0; p < NP; ++p) s[p] = 0.f;

    for (int d = tid; d < DH; d += 256) {
        float g[NV];
#pragma unroll
        for (int j = 0; j < NV; ++j)
            g[j] = fb[(size_t)j * SZ + d] - xb[(size_t)j * SZ + d];
        int p = 0;
#pragma unroll
        for (int j = 0; j < NV; ++j)
#pragma unroll
            for (int l = j; l < NV; ++l) { s[p] += g[j] * g[l]; ++p; }
    }

    // warp reduce then cross-warp reduce
#pragma unroll
    for (int p = 0; p < NP; ++p) {
        float v = s[p];
#pragma unroll
        for (int off = 16; off > 0; off >>= 1)
            v += __shfl_down_sync(0xffffffffu, v, off);
        s[p] = v;
    }
    __shared__ float red[NP][8];
    const int lane = tid & 31, warp = tid >> 5;
    if (lane == 0) {
#pragma unroll
        for (int p = 0; p < NP; ++p) red[p][warp] = s[p];
    }
    __syncthreads();

    if (tid == 0) {
        float GGp[NP];
#pragma unroll
        for (int p = 0; p < NP; ++p) {
            float v = 0.f;
#pragma unroll
            for (int w = 0; w < 8; ++w) v += red[p][w];
            GGp[p] = v;
        }
        // expand triangle to full
        float GG[NV][NV];
        {
            int p = 0;
#pragma unroll
            for (int j = 0; j < NV; ++j)
#pragma unroll
                for (int l = j; l < NV; ++l) { GG[j][l] = GGp[p]; GG[l][j] = GGp[p]; ++p; }
        }
        const int n = NV + 1;
        float Hm[MHIST + 1][MHIST + 2];
        Hm[0][0] = 0.f;
        for (int j = 0; j < NV; ++j) { Hm[0][1 + j] = 1.f; Hm[1 + j][0] = 1.f; }
        for (int j = 0; j < NV; ++j)
            for (int l = 0; l < NV; ++l)
                Hm[1 + j][1 + l] = GG[j][l] + (j == l ? LAM : 0.f);
        for (int r = 0; r < n; ++r) Hm[r][n] = (r == 0) ? 1.f : 0.f;

        // Gaussian elimination with partial pivoting
        for (int c = 0; c < n; ++c) {
            int piv = c; float best = fabsf(Hm[c][c]);
            for (int r = c + 1; r < n; ++r) {
                float v = fabsf(Hm[r][c]);
                if (v > best) { best = v; piv = r; }
            }
            if (piv != c)
                for (int cc = 0; cc <= n; ++cc) {
                    float tmp = Hm[c][cc]; Hm[c][cc] = Hm[piv][cc]; Hm[piv][cc] = tmp;
                }
            float inv = 1.f / Hm[c][c];
            for (int r = c + 1; r < n; ++r) {
                float fct = Hm[r][c] * inv;
                for (int cc = c; cc <= n; ++cc) Hm[r][cc] -= fct * Hm[c][cc];
            }
        }
        float xv[MHIST + 1];
        for (int r = n - 1; r >= 0; --r) {
            float a = Hm[r][n];
            for (int cc = r + 1; cc < n; ++cc) a -= Hm[r][cc] * xv[cc];
            xv[r] = a / Hm[r][r];
        }
#pragma unroll
        for (int j = 0; j < MHIST; ++j)
            g_alpha[row * MHIST + j] = (j < NV) ? xv[1 + j] : 0.f;
    }
}

// ---------------------------------------------------------------------------
// Mix: xk = sum_j alpha[row][j] * F[j][row][:]; write to g_z and g_X[slot].
// One CTA per row, 256 threads * float4 = 1024 floats.
// ---------------------------------------------------------------------------
__global__ void __launch_bounds__(256)
mix_kernel(int nv, int slot)
{
    const int row = blockIdx.x;
    const int tid = threadIdx.x;
    __shared__ float al[MHIST];
    if (tid < MHIST) al[tid] = (tid < nv) ? g_alpha[row * MHIST + tid] : 0.f;
    __syncthreads();

    const size_t base = (size_t)row * DH + tid * 4;
    float4 acc = make_float4(0.f, 0.f, 0.f, 0.f);
    for (int j = 0; j < nv; ++j) {
        const float a = al[j];
        float4 f = *reinterpret_cast<const float4*>(&g_F[(size_t)j * SZ + base]);
        acc.x += a * f.x; acc.y += a * f.y; acc.z += a * f.z; acc.w += a * f.w;
    }
    *reinterpret_cast<float4*>(&g_z[base]) = acc;
    *reinterpret_cast<float4*>(&g_X[(size_t)slot * SZ + base]) = acc;
}

// ---------------------------------------------------------------------------
// Host orchestration
// ---------------------------------------------------------------------------
static void launch_gemm(const float* A, const float* B, const float* bias,
                        float* C, float* C2, int M, int N, int K, bool relu)
{
    dim3 grid(N / 64, M / 128);
    dim3 block(256);
    if (relu) gemm_kernel<true><<<grid, block>>>(A, B, bias, C, C2, N, K);
    else      gemm_kernel<false><<<grid, block>>>(A, B, bias, C, C2, N, K);
}

static void launch_anderson(int nv)
{
    switch (nv) {
        case 2: anderson_kernel<2><<<BATCH, 256>>>(); break;
        case 3: anderson_kernel<3><<<BATCH, 256>>>(); break;
        case 4: anderson_kernel<4><<<BATCH, 256>>>(); break;
        case 5: anderson_kernel<5><<<BATCH, 256>>>(); break;
        default: anderson_kernel<6><<<BATCH, 256>>>(); break;
    }
}

extern "C" void kernel_launch(void* const* d_in, const int* in_sizes, int n_in,
                              void* d_out, int out_size)
{
    const float* x     = (const float*)d_in[0];   // [1024, 512]
    const float* W_in  = (const float*)d_in[1];   // [512, 1024]
    const float* b_in  = (const float*)d_in[2];   // [1024]
    const float* W1    = (const float*)d_in[3];   // [1024, 1024]
    const float* b1    = (const float*)d_in[4];   // [1024]
    const float* W2    = (const float*)d_in[5];   // [1024, 1024]
    const float* b2    = (const float*)d_in[6];   // [1024]
    const float* W_out = (const float*)d_in[7];   // [1024, 512]
    const float* b_out = (const float*)d_in[8];   // [512]
    float* out = (float*)d_out;                   // [1024, 512]

    float *X, *F, *h, *z;
    cudaGetSymbolAddress((void**)&X, g_X);
    cudaGetSymbolAddress((void**)&F, g_F);
    cudaGetSymbolAddress((void**)&h, g_h);
    cudaGetSymbolAddress((void**)&z, g_z);

    // z0 = x @ W_in + b_in  -> X slot 0
    launch_gemm(x, W_in, b_in, X, nullptr, BATCH, DH, DIN, false);
    // F0 = f(X0); X1 = F0  (dual store)
    launch_gemm(X, W1, b1, h, nullptr, BATCH, DH, DH, true);
    launch_gemm(h, W2, b2, F, X + SZ, BATCH, DH, DH, false);
    // F1 = f(X1)
    launch_gemm(X + SZ, W1, b1, h, nullptr, BATCH, DH, DH, true);
    launch_gemm(h, W2, b2, F + SZ, nullptr, BATCH, DH, DH, false);

    for (int k = 2; k < MAXIT; ++k) {
        const int nv   = (k < MHIST) ? k : MHIST;
        const int slot = k % MHIST;
        launch_anderson(nv);
        mix_kernel<<<BATCH, 256>>>(nv, slot);        // xk -> g_z and X[slot]
        if (k < MAXIT - 1) {                          // last f(xk) is dead in the reference
            launch_gemm(z, W1, b1, h, nullptr, BATCH, DH, DH, true);
            launch_gemm(h, W2, b2, F + (size_t)slot * SZ, nullptr, BATCH, DH, DH, false);
        }
    }

    // out = z_star @ W_out + b_out
    launch_gemm(z, W_out, b_out, out, nullptr, BATCH, DOUT, DH, false);
}

// round 8
// speedup vs baseline: 1.5035x; 1.5035x over previous
#include <cuda_runtime.h>
#include <cuda_bf16.h>

// ---------------------------------------------------------------------------
// Problem constants
// ---------------------------------------------------------------------------
#define BATCH 1024
#define DIN   512
#define DH    1024
#define DOUT  512
#define MHIST 6
#define MAXIT 40
#define LAM   1e-4f

#define SZ (BATCH * DH)

// ---------------------------------------------------------------------------
// Scratch (device globals: no runtime allocation allowed)
// ---------------------------------------------------------------------------
__device__ float g_X[MHIST * SZ];     // 24 MB
__device__ float g_F[MHIST * SZ];     // 24 MB
__device__ float g_h[SZ];
__device__ float g_z[SZ];
__device__ float g_alpha[BATCH * MHIST];
// bf16 hi/lo split of W1,W2, transposed to [N,K] K-major
__device__ __nv_bfloat16 g_W1hi[DH * DH], g_W1lo[DH * DH];
__device__ __nv_bfloat16 g_W2hi[DH * DH], g_W2lo[DH * DH];

// ---------------------------------------------------------------------------
// Helpers
// ---------------------------------------------------------------------------
__device__ __forceinline__ unsigned smem_u32(const void* p) {
    unsigned r;
    asm("{ .reg .u64 t; cvta.to.shared.u64 t, %1; cvt.u32.u64 %0, t; }"
        : "=r"(r) : "l"(p));
    return r;
}

// split fp32 pair -> packed bf16x2 hi and lo
__device__ __forceinline__ void split2(float x, float y, unsigned& hi, unsigned& lo) {
    __nv_bfloat16 hx = __float2bfloat16_rn(x), hy = __float2bfloat16_rn(y);
    __nv_bfloat16 lx = __float2bfloat16_rn(x - __bfloat162float(hx));
    __nv_bfloat16 ly = __float2bfloat16_rn(y - __bfloat162float(hy));
    hi = ((unsigned)__bfloat16_as_ushort(hy) << 16) | __bfloat16_as_ushort(hx);
    lo = ((unsigned)__bfloat16_as_ushort(ly) << 16) | __bfloat16_as_ushort(lx);
}

#define LDSM4(r, addr) \
    asm volatile("ldmatrix.sync.aligned.m8n8.x4.shared.b16 {%0,%1,%2,%3}, [%4];" \
        : "=r"((r)[0]), "=r"((r)[1]), "=r"((r)[2]), "=r"((r)[3]) : "r"(addr))
#define LDSM2(r, addr) \
    asm volatile("ldmatrix.sync.aligned.m8n8.x2.shared.b16 {%0,%1}, [%2];" \
        : "=r"((r)[0]), "=r"((r)[1]) : "r"(addr))
#define MMA_BF16(d, a, b) \
    asm volatile("mma.sync.aligned.m16n8k16.row.col.f32.bf16.bf16.f32 " \
        "{%0,%1,%2,%3}, {%4,%5,%6,%7}, {%8,%9}, {%0,%1,%2,%3};" \
        : "+f"((d)[0]), "+f"((d)[1]), "+f"((d)[2]), "+f"((d)[3]) \
        : "r"((a)[0]), "r"((a)[1]), "r"((a)[2]), "r"((a)[3]), \
          "r"((b)[0]), "r"((b)[1]))

// ---------------------------------------------------------------------------
// Weight transpose + bf16 hi/lo split: W[K,N] fp32 -> hiT/loT[N,K] bf16
// ---------------------------------------------------------------------------
__global__ void __launch_bounds__(256)
transsplit_kernel(const float* __restrict__ W,
                  __nv_bfloat16* __restrict__ hiT,
                  __nv_bfloat16* __restrict__ loT)
{
    __shared__ float tile[32][33];
    const int tx = threadIdx.x & 31, ty = threadIdx.x >> 5;
    const int kb = blockIdx.y * 32, nb = blockIdx.x * 32;
#pragma unroll
    for (int r = 0; r < 4; ++r)
        tile[ty + r * 8][tx] = W[(size_t)(kb + ty + r * 8) * DH + nb + tx];
    __syncthreads();
#pragma unroll
    for (int r = 0; r < 4; ++r) {
        const int n = ty + r * 8;
        float v = tile[tx][n];   // W[kb+tx][nb+n]
        __nv_bfloat16 h = __float2bfloat16_rn(v);
        float rr = v - __bfloat162float(h);
        hiT[(size_t)(nb + n) * DH + kb + tx] = h;
        loT[(size_t)(nb + n) * DH + kb + tx] = __float2bfloat16_rn(rr);
    }
}

// ---------------------------------------------------------------------------
// mma.sync bf16 GEMM (3-term split): C[1024,1024] = A[1024,1024](fp32) @ B^T
//   B pre-split bf16 [N,K] K-major. fp32 accumulators.
// CTA tile 128x64, KT=64, double-buffered dynamic SMEM (96 KB).
// Warps: 2(m) x 4(n); warp tile 64x16; mma m16n8k16.
// SMEM stage layout (49152 B): Ah@0 (16K), Al@16384, Bh@32768 (8K), Bl@40960.
// ---------------------------------------------------------------------------
#define STAGE_B 49152
#define SMEM_MMA (2 * STAGE_B)

template <bool RELU, bool DUAL>
__global__ void __launch_bounds__(256, 1)
gemm_mma(const float* __restrict__ A,
         const __nv_bfloat16* __restrict__ Bhi,
         const __nv_bfloat16* __restrict__ Blo,
         const float* __restrict__ bias,
         float* __restrict__ C, float* __restrict__ C2)
{
    constexpr int K = 1024, LDC = 1024, KT = 64, T = K / KT;
    extern __shared__ char smem[];
    const unsigned sbase = smem_u32(smem);
    const int tid = threadIdx.x;
    const int lane = tid & 31, wid = tid >> 5;
    const int warp_m = wid >> 2, warp_n = wid & 3;
    const int m0 = blockIdx.y * 128, n0 = blockIdx.x * 64;

    float acc[4][2][4];
#pragma unroll
    for (int i = 0; i < 4; ++i)
#pragma unroll
        for (int j = 0; j < 2; ++j)
#pragma unroll
            for (int c = 0; c < 4; ++c) acc[i][j][c] = 0.f;

    // ---- loader mapping: 256 threads, 16B output granules ----
    const int lrow = tid >> 3;           // 0..31
    const int lc8  = tid & 7;            // 8-fp32 (=16B bf16) chunk

    float4 pa[4][2];
    uint4  pbh[2], pbl[2];

    auto gload = [&](int t) {
        const int kt = t * KT;
#pragma unroll
        for (int it = 0; it < 4; ++it) {
            const float* src = A + (size_t)(m0 + it * 32 + lrow) * K + kt + lc8 * 8;
            pa[it][0] = *reinterpret_cast<const float4*>(src);
            pa[it][1] = *reinterpret_cast<const float4*>(src + 4);
        }
#pragma unroll
        for (int it = 0; it < 2; ++it) {
            const size_t boff = (size_t)(n0 + it * 32 + lrow) * K + kt + lc8 * 8;
            pbh[it] = *reinterpret_cast<const uint4*>(Bhi + boff);
            pbl[it] = *reinterpret_cast<const uint4*>(Blo + boff);
        }
    };

    auto sstore = [&](int s) {
        char* st = smem + s * STAGE_B;
#pragma unroll
        for (int it = 0; it < 4; ++it) {
            uint4 H, L;
            split2(pa[it][0].x, pa[it][0].y, H.x, L.x);
            split2(pa[it][0].z, pa[it][0].w, H.y, L.y);
            split2(pa[it][1].x, pa[it][1].y, H.z, L.z);
            split2(pa[it][1].z, pa[it][1].w, H.w, L.w);
            unsigned off = (it * 32 + lrow) * 128 + lc8 * 16;
            unsigned sw = off ^ ((off >> 3) & 0x70);
            *reinterpret_cast<uint4*>(st + sw)         = H;
            *reinterpret_cast<uint4*>(st + 16384 + sw) = L;
        }
#pragma unroll
        for (int it = 0; it < 2; ++it) {
            unsigned off = (it * 32 + lrow) * 128 + lc8 * 16;
            unsigned sw = off ^ ((off >> 3) & 0x70);
            *reinterpret_cast<uint4*>(st + 32768 + sw) = pbh[it];
            *reinterpret_cast<uint4*>(st + 40960 + sw) = pbl[it];
        }
    };

    // ---- per-thread ldmatrix offsets ----
    const int lr8 = lane & 7;
    const int lg  = (lane >> 3) & 1;
    const int lcg = lane >> 4;
    unsigned aoff[4];
#pragma unroll
    for (int i = 0; i < 4; ++i)
        aoff[i] = (unsigned)(warp_m * 64 + i * 16 + lr8 + lg * 8) * 128 + lcg * 16;
    unsigned boff[2];
#pragma unroll
    for (int j = 0; j < 2; ++j)
        boff[j] = (unsigned)(warp_n * 16 + j * 8 + lr8) * 128 + lg * 16;

    auto compute = [&](int s) {
        const unsigned st = sbase + s * STAGE_B;
#pragma unroll
        for (int ks = 0; ks < 4; ++ks) {
            unsigned ah[4][4], al[4][4], bh[2][2], bl[2][2];
#pragma unroll
            for (int i = 0; i < 4; ++i) {
                unsigned off = aoff[i] + ks * 32;
                unsigned sw = off ^ ((off >> 3) & 0x70);
                LDSM4(ah[i], st + sw);
                LDSM4(al[i], st + 16384 + sw);
            }
#pragma unroll
            for (int j = 0; j < 2; ++j) {
                unsigned off = boff[j] + ks * 32;
                unsigned sw = off ^ ((off >> 3) & 0x70);
                LDSM2(bh[j], st + 32768 + sw);
                LDSM2(bl[j], st + 40960 + sw);
            }
#pragma unroll
            for (int i = 0; i < 4; ++i)
#pragma unroll
                for (int j = 0; j < 2; ++j) {
                    MMA_BF16(acc[i][j], ah[i], bh[j]);
                    MMA_BF16(acc[i][j], ah[i], bl[j]);
                    MMA_BF16(acc[i][j], al[i], bh[j]);
                }
        }
    };

    // ---- pipelined mainloop ----
    gload(0);
    sstore(0);
    __syncthreads();
    for (int t = 0; t < T; ++t) {
        const int s = t & 1;
        if (t + 1 < T) gload(t + 1);
        compute(s);
        if (t + 1 < T) sstore(s ^ 1);
        __syncthreads();
    }

    // ---- epilogue: bias (+relu), float2 stores ----
    const int erow = lane >> 2;
    const int ecol = (lane & 3) * 2;
#pragma unroll
    for (int i = 0; i < 4; ++i) {
        const int gm = m0 + warp_m * 64 + i * 16 + erow;
#pragma unroll
        for (int j = 0; j < 2; ++j) {
            const int gn = n0 + warp_n * 16 + j * 8 + ecol;
            float2 b2 = *reinterpret_cast<const float2*>(bias + gn);
            float2 v0, v1;
            v0.x = acc[i][j][0] + b2.x; v0.y = acc[i][j][1] + b2.y;
            v1.x = acc[i][j][2] + b2.x; v1.y = acc[i][j][3] + b2.y;
            if (RELU) {
                v0.x = fmaxf(v0.x, 0.f); v0.y = fmaxf(v0.y, 0.f);
                v1.x = fmaxf(v1.x, 0.f); v1.y = fmaxf(v1.y, 0.f);
            }
            const size_t o0 = (size_t)gm * LDC + gn;
            const size_t o1 = (size_t)(gm + 8) * LDC + gn;
            *reinterpret_cast<float2*>(C + o0) = v0;
            *reinterpret_cast<float2*>(C + o1) = v1;
            if (DUAL) {
                *reinterpret_cast<float2*>(C2 + o0) = v0;
                *reinterpret_cast<float2*>(C2 + o1) = v1;
            }
        }
    }
}

// ---------------------------------------------------------------------------
// FP32 SIMT GEMM (in/out projections)
// ---------------------------------------------------------------------------
template <bool RELU>
__global__ void __launch_bounds__(256, 2)
gemm_kernel(const float* __restrict__ A, const float* __restrict__ B,
            const float* __restrict__ bias, float* __restrict__ C,
            float* __restrict__ C2, int N, int K)
{
    constexpr int BM = 128, BN = 64, BK = 16, TM = 8;
    __shared__ float As[BK][BM + 4];
    __shared__ float Bs[BK][BN];

    const int tid = threadIdx.x;
    const int tx  = tid & 15;
    const int ty  = tid >> 4;
    const int m0  = blockIdx.y * BM;
    const int n0  = blockIdx.x * BN;

    const int a_m0 = tid >> 2;
    const int a_m1 = a_m0 + 64;
    const int a_k4 = (tid & 3) * 4;
    const int b_kk = tid >> 4;
    const int b_n  = (tid & 15) * 4;

    unsigned long long acc[TM][2];
#pragma unroll
    for (int i = 0; i < TM; ++i) { acc[i][0] = 0ull; acc[i][1] = 0ull; }

    {
        float4 v0 = *reinterpret_cast<const float4*>(A + (size_t)(m0 + a_m0) * K + a_k4);
        float4 v1 = *reinterpret_cast<const float4*>(A + (size_t)(m0 + a_m1) * K + a_k4);
        As[a_k4 + 0][a_m0] = v0.x; As[a_k4 + 1][a_m0] = v0.y;
        As[a_k4 + 2][a_m0] = v0.z; As[a_k4 + 3][a_m0] = v0.w;
        As[a_k4 + 0][a_m1] = v1.x; As[a_k4 + 1][a_m1] = v1.y;
        As[a_k4 + 2][a_m1] = v1.z; As[a_k4 + 3][a_m1] = v1.w;
        float4 vb = *reinterpret_cast<const float4*>(B + (size_t)b_kk * N + n0 + b_n);
        *reinterpret_cast<float4*>(&Bs[b_kk][b_n]) = vb;
    }
    __syncthreads();

    const int ntiles = K / BK;
    for (int t = 0; t < ntiles; ++t) {
        float4 pa0, pa1, pb;
        const bool has_next = (t + 1 < ntiles);
        if (has_next) {
            const int k0 = (t + 1) * BK;
            pa0 = *reinterpret_cast<const float4*>(A + (size_t)(m0 + a_m0) * K + k0 + a_k4);
            pa1 = *reinterpret_cast<const float4*>(A + (size_t)(m0 + a_m1) * K + k0 + a_k4);
            pb  = *reinterpret_cast<const float4*>(B + (size_t)(k0 + b_kk) * N + n0 + b_n);
        }
#pragma unroll
        for (int kk = 0; kk < BK; ++kk) {
            float4 a0 = *reinterpret_cast<const float4*>(&As[kk][ty * TM]);
            float4 a1 = *reinterpret_cast<const float4*>(&As[kk][ty * TM + 4]);
            ulonglong2 bb = *reinterpret_cast<const ulonglong2*>(&Bs[kk][tx * 4]);
            float av[8] = {a0.x, a0.y, a0.z, a0.w, a1.x, a1.y, a1.z, a1.w};
#pragma unroll
            for (int i = 0; i < 8; ++i) {
                unsigned ai = __float_as_uint(av[i]);
                unsigned long long a2;
                asm("mov.b64 %0, {%1, %2};" : "=l"(a2) : "r"(ai), "r"(ai));
                asm("fma.rn.f32x2 %0, %1, %2, %3;"
                    : "=l"(acc[i][0]) : "l"(a2), "l"(bb.x), "l"(acc[i][0]));
                asm("fma.rn.f32x2 %0, %1, %2, %3;"
                    : "=l"(acc[i][1]) : "l"(a2), "l"(bb.y), "l"(acc[i][1]));
            }
        }
        __syncthreads();
        if (has_next) {
            As[a_k4 + 0][a_m0] = pa0.x; As[a_k4 + 1][a_m0] = pa0.y;
            As[a_k4 + 2][a_m0] = pa0.z; As[a_k4 + 3][a_m0] = pa0.w;
            As[a_k4 + 0][a_m1] = pa1.x; As[a_k4 + 1][a_m1] = pa1.y;
            As[a_k4 + 2][a_m1] = pa1.z; As[a_k4 + 3][a_m1] = pa1.w;
            *reinterpret_cast<float4*>(&Bs[b_kk][b_n]) = pb;
            __syncthreads();
        }
    }

    float4 bs4 = *reinterpret_cast<const float4*>(bias + n0 + tx * 4);
#pragma unroll
    for (int i = 0; i < TM; ++i) {
        unsigned l0, h0, l1, h1;
        asm("mov.b64 {%0, %1}, %2;" : "=r"(l0), "=r"(h0) : "l"(acc[i][0]));
        asm("mov.b64 {%0, %1}, %2;" : "=r"(l1), "=r"(h1) : "l"(acc[i][1]));
        float4 v;
        v.x = __uint_as_float(l0) + bs4.x;
        v.y = __uint_as_float(h0) + bs4.y;
        v.z = __uint_as_float(l1) + bs4.z;
        v.w = __uint_as_float(h1) + bs4.w;
        if (RELU) {
            v.x = fmaxf(v.x, 0.f); v.y = fmaxf(v.y, 0.f);
            v.z = fmaxf(v.z, 0.f); v.w = fmaxf(v.w, 0.f);
        }
        const size_t off = (size_t)(m0 + ty * TM + i) * N + n0 + tx * 4;
        *reinterpret_cast<float4*>(C + off) = v;
        if (C2) *reinterpret_cast<float4*>(C2 + off) = v;
    }
}

// ---------------------------------------------------------------------------
// Anderson alpha
// ---------------------------------------------------------------------------
template <int NV>
__global__ void __launch_bounds__(256)
anderson_kernel()
{
    constexpr int NP = NV * (NV + 1) / 2;
    const int row = blockIdx.x;
    const int tid = threadIdx.x;

    const float* xb = g_X + (size_t)row * DH;
    const float* fb = g_F + (size_t)row * DH;

    float s[NP];
#pragma unroll
    for (int p = 0; p < NP; ++p) s[p] = 0.f;

    for (int d = tid; d < DH; d += 256) {
        float g[NV];
#pragma unroll
        for (int j = 0; j < NV; ++j)
            g[j] = fb[(size_t)j * SZ + d] - xb[(size_t)j * SZ + d];
        int p = 0;
#pragma unroll
        for (int j = 0; j < NV; ++j)
#pragma unroll
            for (int l = j; l < NV; ++l) { s[p] += g[j] * g[l]; ++p; }
    }

#pragma unroll
    for (int p = 0; p < NP; ++p) {
        float v = s[p];
#pragma unroll
        for (int off = 16; off > 0; off >>= 1)
            v += __shfl_down_sync(0xffffffffu, v, off);
        s[p] = v;
    }
    __shared__ float red[NP][8];
    const int lane = tid & 31, warp = tid >> 5;
    if (lane == 0) {
#pragma unroll
        for (int p = 0; p < NP; ++p) red[p][warp] = s[p];
    }
    __syncthreads();

    if (tid == 0) {
        float GGp[NP];
#pragma unroll
        for (int p = 0; p < NP; ++p) {
            float v = 0.f;
#pragma unroll
            for (int w = 0; w < 8; ++w) v += red[p][w];
            GGp[p] = v;
        }
        float GG[NV][NV];
        {
            int p = 0;
#pragma unroll
            for (int j = 0; j < NV; ++j)
#pragma unroll
                for (int l = j; l < NV; ++l) { GG[j][l] = GGp[p]; GG[l][j] = GGp[p]; ++p; }
        }
        const int n = NV + 1;
        float Hm[MHIST + 1][MHIST + 2];
        Hm[0][0] = 0.f;
        for (int j = 0; j < NV; ++j) { Hm[0][1 + j] = 1.f; Hm[1 + j][0] = 1.f; }
        for (int j = 0; j < NV; ++j)
            for (int l = 0; l < NV; ++l)
                Hm[1 + j][1 + l] = GG[j][l] + (j == l ? LAM : 0.f);
        for (int r = 0; r < n; ++r) Hm[r][n] = (r == 0) ? 1.f : 0.f;

        for (int c = 0; c < n; ++c) {
            int piv = c; float best = fabsf(Hm[c][c]);
            for (int r = c + 1; r < n; ++r) {
                float v = fabsf(Hm[r][c]);
                if (v > best) { best = v; piv = r; }
            }
            if (piv != c)
                for (int cc = 0; cc <= n; ++cc) {
                    float tmp = Hm[c][cc]; Hm[c][cc] = Hm[piv][cc]; Hm[piv][cc] = tmp;
                }
            float inv = 1.f / Hm[c][c];
            for (int r = c + 1; r < n; ++r) {
                float fct = Hm[r][c] * inv;
                for (int cc = c; cc <= n; ++cc) Hm[r][cc] -= fct * Hm[c][cc];
            }
        }
        float xv[MHIST + 1];
        for (int r = n - 1; r >= 0; --r) {
            float a = Hm[r][n];
            for (int cc = r + 1; cc < n; ++cc) a -= Hm[r][cc] * xv[cc];
            xv[r] = a / Hm[r][r];
        }
#pragma unroll
        for (int j = 0; j < MHIST; ++j)
            g_alpha[row * MHIST + j] = (j < NV) ? xv[1 + j] : 0.f;
    }
}

// ---------------------------------------------------------------------------
// Mix: xk = sum_j alpha[row][j] * F[j][row][:]; write to g_z and g_X[slot]
// ---------------------------------------------------------------------------
__global__ void __launch_bounds__(256)
mix_kernel(int nv, int slot)
{
    const int row = blockIdx.x;
    const int tid = threadIdx.x;
    __shared__ float al[MHIST];
    if (tid < MHIST) al[tid] = (tid < nv) ? g_alpha[row * MHIST + tid] : 0.f;
    __syncthreads();

    const size_t base = (size_t)row * DH + tid * 4;
    float4 acc = make_float4(0.f, 0.f, 0.f, 0.f);
    for (int j = 0; j < nv; ++j) {
        const float a = al[j];
        float4 f = *reinterpret_cast<const float4*>(&g_F[(size_t)j * SZ + base]);
        acc.x += a * f.x; acc.y += a * f.y; acc.z += a * f.z; acc.w += a * f.w;
    }
    *reinterpret_cast<float4*>(&g_z[base]) = acc;
    *reinterpret_cast<float4*>(&g_X[(size_t)slot * SZ + base]) = acc;
}

// ---------------------------------------------------------------------------
// Host orchestration
// ---------------------------------------------------------------------------
static void launch_gemm(const float* A, const float* B, const float* bias,
                        float* C, float* C2, int M, int N, int K, bool relu)
{
    dim3 grid(N / 64, M / 128);
    if (relu) gemm_kernel<true><<<grid, 256>>>(A, B, bias, C, C2, N, K);
    else      gemm_kernel<false><<<grid, 256>>>(A, B, bias, C, C2, N, K);
}

static void launch_anderson(int nv)
{
    switch (nv) {
        case 2: anderson_kernel<2><<<BATCH, 256>>>(); break;
        case 3: anderson_kernel<3><<<BATCH, 256>>>(); break;
        case 4: anderson_kernel<4><<<BATCH, 256>>>(); break;
        case 5: anderson_kernel<5><<<BATCH, 256>>>(); break;
        default: anderson_kernel<6><<<BATCH, 256>>>(); break;
    }
}

extern "C" void kernel_launch(void* const* d_in, const int* in_sizes, int n_in,
                              void* d_out, int out_size)
{
    const float* x     = (const float*)d_in[0];
    const float* W_in  = (const float*)d_in[1];
    const float* b_in  = (const float*)d_in[2];
    const float* W1    = (const float*)d_in[3];
    const float* b1    = (const float*)d_in[4];
    const float* W2    = (const float*)d_in[5];
    const float* b2    = (const float*)d_in[6];
    const float* W_out = (const float*)d_in[7];
    const float* b_out = (const float*)d_in[8];
    float* out = (float*)d_out;

    float *X, *F, *h, *z;
    __nv_bfloat16 *W1hi, *W1lo, *W2hi, *W2lo;
    cudaGetSymbolAddress((void**)&X, g_X);
    cudaGetSymbolAddress((void**)&F, g_F);
    cudaGetSymbolAddress((void**)&h, g_h);
    cudaGetSymbolAddress((void**)&z, g_z);
    cudaGetSymbolAddress((void**)&W1hi, g_W1hi);
    cudaGetSymbolAddress((void**)&W1lo, g_W1lo);
    cudaGetSymbolAddress((void**)&W2hi, g_W2hi);
    cudaGetSymbolAddress((void**)&W2lo, g_W2lo);

    cudaFuncSetAttribute(gemm_mma<true, false>,
                         cudaFuncAttributeMaxDynamicSharedMemorySize, SMEM_MMA);
    cudaFuncSetAttribute(gemm_mma<false, false>,
                         cudaFuncAttributeMaxDynamicSharedMemorySize, SMEM_MMA);
    cudaFuncSetAttribute(gemm_mma<false, true>,
                         cudaFuncAttributeMaxDynamicSharedMemorySize, SMEM_MMA);

    // one-time weight transpose + split
    transsplit_kernel<<<dim3(32, 32), 256>>>(W1, W1hi, W1lo);
    transsplit_kernel<<<dim3(32, 32), 256>>>(W2, W2hi, W2lo);

    const dim3 tcg(16, 8);   // N/64, M/128

    // z0 = x @ W_in + b_in  -> X slot 0 (exact fp32)
    launch_gemm(x, W_in, b_in, X, nullptr, BATCH, DH, DIN, false);

    // F0 = f(X0); X1 = F0 (dual store)
    gemm_mma<true,  false><<<tcg, 256, SMEM_MMA>>>(X, W1hi, W1lo, b1, h, nullptr);
    gemm_mma<false, true ><<<tcg, 256, SMEM_MMA>>>(h, W2hi, W2lo, b2, F, X + SZ);
    // F1 = f(X1)
    gemm_mma<true,  false><<<tcg, 256, SMEM_MMA>>>(X + SZ, W1hi, W1lo, b1, h, nullptr);
    gemm_mma<false, false><<<tcg, 256, SMEM_MMA>>>(h, W2hi, W2lo, b2, F + SZ, nullptr);

    for (int k = 2; k < MAXIT; ++k) {
        const int nv   = (k < MHIST) ? k : MHIST;
        const int slot = k % MHIST;
        launch_anderson(nv);
        mix_kernel<<<BATCH, 256>>>(nv, slot);
        if (k < MAXIT - 1) {
            gemm_mma<true,  false><<<tcg, 256, SMEM_MMA>>>(z, W1hi, W1lo, b1, h, nullptr);
            gemm_mma<false, false><<<tcg, 256, SMEM_MMA>>>(h, W2hi, W2lo, b2,
                                                           F + (size_t)slot * SZ, nullptr);
        }
    }

    // out = z_star @ W_out + b_out (exact fp32)
    launch_gemm(z, W_out, b_out, out, nullptr, BATCH, DOUT, DH, false);
}

// round 9
// speedup vs baseline: 2.2984x; 1.5287x over previous
#include <cuda_runtime.h>
#include <cuda_bf16.h>

// ---------------------------------------------------------------------------
// Problem constants
// ---------------------------------------------------------------------------
#define BATCH 1024
#define DIN   512
#define DH    1024
#define DOUT  512
#define MHIST 6
#define MAXIT 40
#define LAM   1e-4f

#define SZ (BATCH * DH)

// ---------------------------------------------------------------------------
// Scratch (device globals: no runtime allocation allowed)
// ---------------------------------------------------------------------------
__device__ float g_X[MHIST * SZ];     // 24 MB
__device__ float g_F[MHIST * SZ];     // 24 MB
__device__ float g_z[SZ];
__device__ float g_alpha[BATCH * MHIST];
// bf16 hi/lo split operands
__device__ __nv_bfloat16 g_Ahi[SZ], g_Alo[SZ];   // current z-like operand
__device__ __nv_bfloat16 g_Hhi[SZ], g_Hlo[SZ];   // hidden activations
// bf16 hi/lo split of W1,W2, transposed to [N,K] K-major
__device__ __nv_bfloat16 g_W1hi[DH * DH], g_W1lo[DH * DH];
__device__ __nv_bfloat16 g_W2hi[DH * DH], g_W2lo[DH * DH];

// ---------------------------------------------------------------------------
// Helpers
// ---------------------------------------------------------------------------
__device__ __forceinline__ unsigned smem_u32(const void* p) {
    unsigned r;
    asm("{ .reg .u64 t; cvta.to.shared.u64 t, %1; cvt.u32.u64 %0, t; }"
        : "=r"(r) : "l"(p));
    return r;
}

// split fp32 pair -> packed bf16x2 hi and lo
__device__ __forceinline__ void split2(float x, float y, unsigned& hi, unsigned& lo) {
    __nv_bfloat16 hx = __float2bfloat16_rn(x), hy = __float2bfloat16_rn(y);
    __nv_bfloat16 lx = __float2bfloat16_rn(x - __bfloat162float(hx));
    __nv_bfloat16 ly = __float2bfloat16_rn(y - __bfloat162float(hy));
    hi = ((unsigned)__bfloat16_as_ushort(hy) << 16) | __bfloat16_as_ushort(hx);
    lo = ((unsigned)__bfloat16_as_ushort(ly) << 16) | __bfloat16_as_ushort(lx);
}

#define LDSM4(r, addr) \
    asm volatile("ldmatrix.sync.aligned.m8n8.x4.shared.b16 {%0,%1,%2,%3}, [%4];" \
        : "=r"((r)[0]), "=r"((r)[1]), "=r"((r)[2]), "=r"((r)[3]) : "r"(addr))
#define LDSM2(r, addr) \
    asm volatile("ldmatrix.sync.aligned.m8n8.x2.shared.b16 {%0,%1}, [%2];" \
        : "=r"((r)[0]), "=r"((r)[1]) : "r"(addr))
#define MMA_BF16(d, a, b) \
    asm volatile("mma.sync.aligned.m16n8k16.row.col.f32.bf16.bf16.f32 " \
        "{%0,%1,%2,%3}, {%4,%5,%6,%7}, {%8,%9}, {%0,%1,%2,%3};" \
        : "+f"((d)[0]), "+f"((d)[1]), "+f"((d)[2]), "+f"((d)[3]) \
        : "r"((a)[0]), "r"((a)[1]), "r"((a)[2]), "r"((a)[3]), \
          "r"((b)[0]), "r"((b)[1]))

#define CP_ASYNC16(dst, src) \
    asm volatile("cp.async.cg.shared.global [%0], [%1], 16;" \
        :: "r"(dst), "l"(src) : "memory")
#define CP_COMMIT() asm volatile("cp.async.commit_group;" ::: "memory")
#define CP_WAIT2()  asm volatile("cp.async.wait_group 2;"  ::: "memory")

// ---------------------------------------------------------------------------
// Weight transpose + bf16 hi/lo split: W[K,N] fp32 -> hiT/loT[N,K] bf16
// ---------------------------------------------------------------------------
__global__ void __launch_bounds__(256)
transsplit_kernel(const float* __restrict__ W,
                  __nv_bfloat16* __restrict__ hiT,
                  __nv_bfloat16* __restrict__ loT)
{
    __shared__ float tile[32][33];
    const int tx = threadIdx.x & 31, ty = threadIdx.x >> 5;
    const int kb = blockIdx.y * 32, nb = blockIdx.x * 32;
#pragma unroll
    for (int r = 0; r < 4; ++r)
        tile[ty + r * 8][tx] = W[(size_t)(kb + ty + r * 8) * DH + nb + tx];
    __syncthreads();
#pragma unroll
    for (int r = 0; r < 4; ++r) {
        const int n = ty + r * 8;
        float v = tile[tx][n];   // W[kb+tx][nb+n]
        __nv_bfloat16 h = __float2bfloat16_rn(v);
        float rr = v - __bfloat162float(h);
        hiT[(size_t)(nb + n) * DH + kb + tx] = h;
        loT[(size_t)(nb + n) * DH + kb + tx] = __float2bfloat16_rn(rr);
    }
}

// ---------------------------------------------------------------------------
// mma.sync bf16 GEMM (3-term split), all operands pre-split bf16.
//   D = Ahi*Bhi + Ahi*Blo + Alo*Bhi, fp32 accum.
// A[M,K] K-major bf16 (hi/lo), B[N,K] K-major bf16 (hi/lo).
// CTA tile 128x64, KT=64, 4-stage cp.async pipeline (192 KB smem).
// Warps: 2(m) x 4(n); warp tile 64x16; mma m16n8k16.
// Stage layout (49152 B): Ah@0 (16K), Al@16384, Bh@32768 (8K), Bl@40960.
// Epilogue: optional fp32 C, fp32 C2, and bf16 hi/lo split outputs.
// ---------------------------------------------------------------------------
#define STAGE_B 49152
#define NSTAGES 4
#define SMEM_MMA (NSTAGES * STAGE_B)

template <bool RELU>
__global__ void __launch_bounds__(256, 1)
gemm_mma(const __nv_bfloat16* __restrict__ Ahi,
         const __nv_bfloat16* __restrict__ Alo,
         const __nv_bfloat16* __restrict__ Bhi,
         const __nv_bfloat16* __restrict__ Blo,
         const float* __restrict__ bias,
         float* __restrict__ C, float* __restrict__ C2,
         __nv_bfloat16* __restrict__ Shi, __nv_bfloat16* __restrict__ Slo)
{
    constexpr int K = 1024, LDC = 1024, KT = 64, T = K / KT;
    extern __shared__ char smem[];
    const unsigned sbase = smem_u32(smem);
    const int tid = threadIdx.x;
    const int lane = tid & 31, wid = tid >> 5;
    const int warp_m = wid >> 2, warp_n = wid & 3;
    const int m0 = blockIdx.y * 128, n0 = blockIdx.x * 64;

    float acc[4][2][4];
#pragma unroll
    for (int i = 0; i < 4; ++i)
#pragma unroll
        for (int j = 0; j < 2; ++j)
#pragma unroll
            for (int c = 0; c < 4; ++c) acc[i][j][c] = 0.f;

    // loader mapping: 256 threads, 16B granules; rows of 128B (64 bf16)
    const int lrow = tid >> 3;   // 0..31
    const int lc16 = tid & 7;    // 16B chunk within row

    auto load_stage = [&](int t, int s) {
        const int kt = t * KT;
        const unsigned stb = sbase + s * STAGE_B;
        const unsigned off0 = lrow * 128 + lc16 * 16;
#pragma unroll
        for (int it = 0; it < 4; ++it) {
            unsigned off = off0 + it * 32 * 128;
            unsigned sw = (off ^ ((off >> 3) & 0x70)) - it * 32 * 128;
            const size_t goff = (size_t)(m0 + it * 32 + lrow) * K + kt + lc16 * 8;
            CP_ASYNC16(stb + it * 4096 + sw, Ahi + goff);
            CP_ASYNC16(stb + 16384 + it * 4096 + sw, Alo + goff);
        }
#pragma unroll
        for (int it = 0; it < 2; ++it) {
            unsigned off = off0 + it * 32 * 128;
            unsigned sw = (off ^ ((off >> 3) & 0x70)) - it * 32 * 128;
            const size_t goff = (size_t)(n0 + it * 32 + lrow) * K + kt + lc16 * 8;
            CP_ASYNC16(stb + 32768 + it * 4096 + sw, Bhi + goff);
            CP_ASYNC16(stb + 40960 + it * 4096 + sw, Blo + goff);
        }
    };

    // per-thread ldmatrix offsets
    const int lr8 = lane & 7;
    const int lg  = (lane >> 3) & 1;
    const int lcg = lane >> 4;
    unsigned aoff[4];
#pragma unroll
    for (int i = 0; i < 4; ++i)
        aoff[i] = (unsigned)(warp_m * 64 + i * 16 + lr8 + lg * 8) * 128 + lcg * 16;
    unsigned boff[2];
#pragma unroll
    for (int j = 0; j < 2; ++j)
        boff[j] = (unsigned)(warp_n * 16 + j * 8 + lr8) * 128 + lg * 16;

    auto compute = [&](int s) {
        const unsigned st = sbase + s * STAGE_B;
#pragma unroll
        for (int ks = 0; ks < 4; ++ks) {
            unsigned ah[4][4], al[4][4], bh[2][2], bl[2][2];
#pragma unroll
            for (int i = 0; i < 4; ++i) {
                unsigned off = aoff[i] + ks * 32;
                unsigned sw = off ^ ((off >> 3) & 0x70);
                LDSM4(ah[i], st + sw);
                LDSM4(al[i], st + 16384 + sw);
            }
#pragma unroll
            for (int j = 0; j < 2; ++j) {
                unsigned off = boff[j] + ks * 32;
                unsigned sw = off ^ ((off >> 3) & 0x70);
                LDSM2(bh[j], st + 32768 + sw);
                LDSM2(bl[j], st + 40960 + sw);
            }
#pragma unroll
            for (int i = 0; i < 4; ++i)
#pragma unroll
                for (int j = 0; j < 2; ++j) {
                    MMA_BF16(acc[i][j], ah[i], bh[j]);
                    MMA_BF16(acc[i][j], ah[i], bl[j]);
                    MMA_BF16(acc[i][j], al[i], bh[j]);
                }
        }
    };

    // ---- 4-stage cp.async mainloop ----
#pragma unroll
    for (int s = 0; s < NSTAGES - 1; ++s) {
        load_stage(s, s);
        CP_COMMIT();
    }
    for (int t = 0; t < T; ++t) {
        CP_WAIT2();
        __syncthreads();
        if (t + NSTAGES - 1 < T) load_stage(t + NSTAGES - 1, (t + NSTAGES - 1) & (NSTAGES - 1));
        CP_COMMIT();
        compute(t & (NSTAGES - 1));
    }

    // ---- epilogue ----
    const int erow = lane >> 2;
    const int ecol = (lane & 3) * 2;
#pragma unroll
    for (int i = 0; i < 4; ++i) {
        const int gm = m0 + warp_m * 64 + i * 16 + erow;
#pragma unroll
        for (int j = 0; j < 2; ++j) {
            const int gn = n0 + warp_n * 16 + j * 8 + ecol;
            float2 b2 = *reinterpret_cast<const float2*>(bias + gn);
            float2 v0, v1;
            v0.x = acc[i][j][0] + b2.x; v0.y = acc[i][j][1] + b2.y;
            v1.x = acc[i][j][2] + b2.x; v1.y = acc[i][j][3] + b2.y;
            if (RELU) {
                v0.x = fmaxf(v0.x, 0.f); v0.y = fmaxf(v0.y, 0.f);
                v1.x = fmaxf(v1.x, 0.f); v1.y = fmaxf(v1.y, 0.f);
            }
            const size_t o0 = (size_t)gm * LDC + gn;
            const size_t o1 = (size_t)(gm + 8) * LDC + gn;
            if (C) {
                *reinterpret_cast<float2*>(C + o0) = v0;
                *reinterpret_cast<float2*>(C + o1) = v1;
            }
            if (C2) {
                *reinterpret_cast<float2*>(C2 + o0) = v0;
                *reinterpret_cast<float2*>(C2 + o1) = v1;
            }
            if (Shi) {
                unsigned h0, l0, h1, l1;
                split2(v0.x, v0.y, h0, l0);
                split2(v1.x, v1.y, h1, l1);
                *reinterpret_cast<unsigned*>(Shi + o0) = h0;
                *reinterpret_cast<unsigned*>(Slo + o0) = l0;
                *reinterpret_cast<unsigned*>(Shi + o1) = h1;
                *reinterpret_cast<unsigned*>(Slo + o1) = l1;
            }
        }
    }
}

// ---------------------------------------------------------------------------
// FP32 SIMT GEMM (in/out projections), optional bf16 split output
// ---------------------------------------------------------------------------
template <bool RELU>
__global__ void __launch_bounds__(256, 2)
gemm_kernel(const float* __restrict__ A, const float* __restrict__ B,
            const float* __restrict__ bias, float* __restrict__ C,
            __nv_bfloat16* __restrict__ Shi, __nv_bfloat16* __restrict__ Slo,
            int N, int K)
{
    constexpr int BM = 128, BN = 64, BK = 16, TM = 8;
    __shared__ float As[BK][BM + 4];
    __shared__ float Bs[BK][BN];

    const int tid = threadIdx.x;
    const int tx  = tid & 15;
    const int ty  = tid >> 4;
    const int m0  = blockIdx.y * BM;
    const int n0  = blockIdx.x * BN;

    const int a_m0 = tid >> 2;
    const int a_m1 = a_m0 + 64;
    const int a_k4 = (tid & 3) * 4;
    const int b_kk = tid >> 4;
    const int b_n  = (tid & 15) * 4;

    unsigned long long acc[TM][2];
#pragma unroll
    for (int i = 0; i < TM; ++i) { acc[i][0] = 0ull; acc[i][1] = 0ull; }

    {
        float4 v0 = *reinterpret_cast<const float4*>(A + (size_t)(m0 + a_m0) * K + a_k4);
        float4 v1 = *reinterpret_cast<const float4*>(A + (size_t)(m0 + a_m1) * K + a_k4);
        As[a_k4 + 0][a_m0] = v0.x; As[a_k4 + 1][a_m0] = v0.y;
        As[a_k4 + 2][a_m0] = v0.z; As[a_k4 + 3][a_m0] = v0.w;
        As[a_k4 + 0][a_m1] = v1.x; As[a_k4 + 1][a_m1] = v1.y;
        As[a_k4 + 2][a_m1] = v1.z; As[a_k4 + 3][a_m1] = v1.w;
        float4 vb = *reinterpret_cast<const float4*>(B + (size_t)b_kk * N + n0 + b_n);
        *reinterpret_cast<float4*>(&Bs[b_kk][b_n]) = vb;
    }
    __syncthreads();

    const int ntiles = K / BK;
    for (int t = 0; t < ntiles; ++t) {
        float4 pa0, pa1, pb;
        const bool has_next = (t + 1 < ntiles);
        if (has_next) {
            const int k0 = (t + 1) * BK;
            pa0 = *reinterpret_cast<const float4*>(A + (size_t)(m0 + a_m0) * K + k0 + a_k4);
            pa1 = *reinterpret_cast<const float4*>(A + (size_t)(m0 + a_m1) * K + k0 + a_k4);
            pb  = *reinterpret_cast<const float4*>(B + (size_t)(k0 + b_kk) * N + n0 + b_n);
        }
#pragma unroll
        for (int kk = 0; kk < BK; ++kk) {
            float4 a0 = *reinterpret_cast<const float4*>(&As[kk][ty * TM]);
            float4 a1 = *reinterpret_cast<const float4*>(&As[kk][ty * TM + 4]);
            ulonglong2 bb = *reinterpret_cast<const ulonglong2*>(&Bs[kk][tx * 4]);
            float av[8] = {a0.x, a0.y, a0.z, a0.w, a1.x, a1.y, a1.z, a1.w};
#pragma unroll
            for (int i = 0; i < 8; ++i) {
                unsigned ai = __float_as_uint(av[i]);
                unsigned long long a2;
                asm("mov.b64 %0, {%1, %2};" : "=l"(a2) : "r"(ai), "r"(ai));
                asm("fma.rn.f32x2 %0, %1, %2, %3;"
                    : "=l"(acc[i][0]) : "l"(a2), "l"(bb.x), "l"(acc[i][0]));
                asm("fma.rn.f32x2 %0, %1, %2, %3;"
                    : "=l"(acc[i][1]) : "l"(a2), "l"(bb.y), "l"(acc[i][1]));
            }
        }
        __syncthreads();
        if (has_next) {
            As[a_k4 + 0][a_m0] = pa0.x; As[a_k4 + 1][a_m0] = pa0.y;
            As[a_k4 + 2][a_m0] = pa0.z; As[a_k4 + 3][a_m0] = pa0.w;
            As[a_k4 + 0][a_m1] = pa1.x; As[a_k4 + 1][a_m1] = pa1.y;
            As[a_k4 + 2][a_m1] = pa1.z; As[a_k4 + 3][a_m1] = pa1.w;
            *reinterpret_cast<float4*>(&Bs[b_kk][b_n]) = pb;
            __syncthreads();
        }
    }

    float4 bs4 = *reinterpret_cast<const float4*>(bias + n0 + tx * 4);
#pragma unroll
    for (int i = 0; i < TM; ++i) {
        unsigned l0, h0, l1, h1;
        asm("mov.b64 {%0, %1}, %2;" : "=r"(l0), "=r"(h0) : "l"(acc[i][0]));
        asm("mov.b64 {%0, %1}, %2;" : "=r"(l1), "=r"(h1) : "l"(acc[i][1]));
        float4 v;
        v.x = __uint_as_float(l0) + bs4.x;
        v.y = __uint_as_float(h0) + bs4.y;
        v.z = __uint_as_float(l1) + bs4.z;
        v.w = __uint_as_float(h1) + bs4.w;
        if (RELU) {
            v.x = fmaxf(v.x, 0.f); v.y = fmaxf(v.y, 0.f);
            v.z = fmaxf(v.z, 0.f); v.w = fmaxf(v.w, 0.f);
        }
        const size_t off = (size_t)(m0 + ty * TM + i) * N + n0 + tx * 4;
        *reinterpret_cast<float4*>(C + off) = v;
        if (Shi) {
            unsigned sh0, sl0, sh1, sl1;
            split2(v.x, v.y, sh0, sl0);
            split2(v.z, v.w, sh1, sl1);
            *reinterpret_cast<uint2*>(Shi + off) = make_uint2(sh0, sh1);
            *reinterpret_cast<uint2*>(Slo + off) = make_uint2(sl0, sl1);
        }
    }
}

// ---------------------------------------------------------------------------
// Fused Anderson alpha + mix: one CTA per batch row.
// Computes alpha from the bordered system, then xk = sum_j alpha_j F[j],
// writes xk to g_z (fp32), g_X[slot] (fp32), and g_Ahi/g_Alo (bf16 split).
// ---------------------------------------------------------------------------
template <int NV>
__global__ void __launch_bounds__(256)
anderson_mix_kernel(int slot)
{
    constexpr int NP = NV * (NV + 1) / 2;
    const int row = blockIdx.x;
    const int tid = threadIdx.x;

    const float* xb = g_X + (size_t)row * DH;
    const float* fb = g_F + (size_t)row * DH;

    float s[NP];
#pragma unroll
    for (int p = 0; p < NP; ++p) s[p] = 0.f;

    for (int d = tid; d < DH; d += 256) {
        float g[NV];
#pragma unroll
        for (int j = 0; j < NV; ++j)
            g[j] = fb[(size_t)j * SZ + d] - xb[(size_t)j * SZ + d];
        int p = 0;
#pragma unroll
        for (int j = 0; j < NV; ++j)
#pragma unroll
            for (int l = j; l < NV; ++l) { s[p] += g[j] * g[l]; ++p; }
    }

#pragma unroll
    for (int p = 0; p < NP; ++p) {
        float v = s[p];
#pragma unroll
        for (int off = 16; off > 0; off >>= 1)
            v += __shfl_down_sync(0xffffffffu, v, off);
        s[p] = v;
    }
    __shared__ float red[NP][8];
    __shared__ float al[NV];
    const int lane = tid & 31, warp = tid >> 5;
    if (lane == 0) {
#pragma unroll
        for (int p = 0; p < NP; ++p) red[p][warp] = s[p];
    }
    __syncthreads();

    if (tid == 0) {
        float GGp[NP];
#pragma unroll
        for (int p = 0; p < NP; ++p) {
            float v = 0.f;
#pragma unroll
            for (int w = 0; w < 8; ++w) v += red[p][w];
            GGp[p] = v;
        }
        float GG[NV][NV];
        {
            int p = 0;
#pragma unroll
            for (int j = 0; j < NV; ++j)
#pragma unroll
                for (int l = j; l < NV; ++l) { GG[j][l] = GGp[p]; GG[l][j] = GGp[p]; ++p; }
        }
        const int n = NV + 1;
        float Hm[MHIST + 1][MHIST + 2];
        Hm[0][0] = 0.f;
        for (int j = 0; j < NV; ++j) { Hm[0][1 + j] = 1.f; Hm[1 + j][0] = 1.f; }
        for (int j = 0; j < NV; ++j)
            for (int l = 0; l < NV; ++l)
                Hm[1 + j][1 + l] = GG[j][l] + (j == l ? LAM : 0.f);
        for (int r = 0; r < n; ++r) Hm[r][n] = (r == 0) ? 1.f : 0.f;

        for (int c = 0; c < n; ++c) {
            int piv = c; float best = fabsf(Hm[c][c]);
            for (int r = c + 1; r < n; ++r) {
                float v = fabsf(Hm[r][c]);
                if (v > best) { best = v; piv = r; }
            }
            if (piv != c)
                for (int cc = 0; cc <= n; ++cc) {
                    float tmp = Hm[c][cc]; Hm[c][cc] = Hm[piv][cc]; Hm[piv][cc] = tmp;
                }
            float inv = 1.f / Hm[c][c];
            for (int r = c + 1; r < n; ++r) {
                float fct = Hm[r][c] * inv;
                for (int cc = c; cc <= n; ++cc) Hm[r][cc] -= fct * Hm[c][cc];
            }
        }
        float xv[MHIST + 1];
        for (int r = n - 1; r >= 0; --r) {
            float a = Hm[r][n];
            for (int cc = r + 1; cc < n; ++cc) a -= Hm[r][cc] * xv[cc];
            xv[r] = a / Hm[r][r];
        }
#pragma unroll
        for (int j = 0; j < NV; ++j) al[j] = xv[1 + j];
    }
    __syncthreads();

    // mix: xk = sum_j al[j] * F[j][row][:], 256 threads x float4
    const size_t base = (size_t)row * DH + tid * 4;
    float4 acc = make_float4(0.f, 0.f, 0.f, 0.f);
#pragma unroll
    for (int j = 0; j < NV; ++j) {
        const float a = al[j];
        float4 f = *reinterpret_cast<const float4*>(&g_F[(size_t)j * SZ + base]);
        acc.x += a * f.x; acc.y += a * f.y; acc.z += a * f.z; acc.w += a * f.w;
    }
    *reinterpret_cast<float4*>(&g_z[base]) = acc;
    *reinterpret_cast<float4*>(&g_X[(size_t)slot * SZ + base]) = acc;
    unsigned h0, l0, h1, l1;
    split2(acc.x, acc.y, h0, l0);
    split2(acc.z, acc.w, h1, l1);
    *reinterpret_cast<uint2*>(g_Ahi + base) = make_uint2(h0, h1);
    *reinterpret_cast<uint2*>(g_Alo + base) = make_uint2(l0, l1);
}

// ---------------------------------------------------------------------------
// Host orchestration
// ---------------------------------------------------------------------------
static void launch_anderson_mix(int nv, int slot)
{
    switch (nv) {
        case 2: anderson_mix_kernel<2><<<BATCH, 256>>>(slot); break;
        case 3: anderson_mix_kernel<3><<<BATCH, 256>>>(slot); break;
        case 4: anderson_mix_kernel<4><<<BATCH, 256>>>(slot); break;
        case 5: anderson_mix_kernel<5><<<BATCH, 256>>>(slot); break;
        default: anderson_mix_kernel<6><<<BATCH, 256>>>(slot); break;
    }
}

extern "C" void kernel_launch(void* const* d_in, const int* in_sizes, int n_in,
                              void* d_out, int out_size)
{
    const float* x     = (const float*)d_in[0];
    const float* W_in  = (const float*)d_in[1];
    const float* b_in  = (const float*)d_in[2];
    const float* W1    = (const float*)d_in[3];
    const float* b1    = (const float*)d_in[4];
    const float* W2    = (const float*)d_in[5];
    const float* b2    = (const float*)d_in[6];
    const float* W_out = (const float*)d_in[7];
    const float* b_out = (const float*)d_in[8];
    float* out = (float*)d_out;

    float *X, *F, *z;
    __nv_bfloat16 *Ahi, *Alo, *Hhi, *Hlo, *W1hi, *W1lo, *W2hi, *W2lo;
    cudaGetSymbolAddress((void**)&X, g_X);
    cudaGetSymbolAddress((void**)&F, g_F);
    cudaGetSymbolAddress((void**)&z, g_z);
    cudaGetSymbolAddress((void**)&Ahi, g_Ahi);
    cudaGetSymbolAddress((void**)&Alo, g_Alo);
    cudaGetSymbolAddress((void**)&Hhi, g_Hhi);
    cudaGetSymbolAddress((void**)&Hlo, g_Hlo);
    cudaGetSymbolAddress((void**)&W1hi, g_W1hi);
    cudaGetSymbolAddress((void**)&W1lo, g_W1lo);
    cudaGetSymbolAddress((void**)&W2hi, g_W2hi);
    cudaGetSymbolAddress((void**)&W2lo, g_W2lo);

    cudaFuncSetAttribute(gemm_mma<true>,
                         cudaFuncAttributeMaxDynamicSharedMemorySize, SMEM_MMA);
    cudaFuncSetAttribute(gemm_mma<false>,
                         cudaFuncAttributeMaxDynamicSharedMemorySize, SMEM_MMA);

    // one-time weight transpose + split
    transsplit_kernel<<<dim3(32, 32), 256>>>(W1, W1hi, W1lo);
    transsplit_kernel<<<dim3(32, 32), 256>>>(W2, W2hi, W2lo);

    const dim3 tcg(16, 8);   // N/64, M/128

    // z0 = x @ W_in + b_in -> X[0] fp32 + split -> A
    gemm_kernel<false><<<dim3(DH / 64, BATCH / 128), 256>>>(
        x, W_in, b_in, X, Ahi, Alo, DH, DIN);

    // F0 = f(X0); X1 = F0 (dual store + split -> A)
    gemm_mma<true ><<<tcg, 256, SMEM_MMA>>>(Ahi, Alo, W1hi, W1lo, b1,
                                            nullptr, nullptr, Hhi, Hlo);
    gemm_mma<false><<<tcg, 256, SMEM_MMA>>>(Hhi, Hlo, W2hi, W2lo, b2,
                                            F, X + SZ, Ahi, Alo);
    // F1 = f(X1)
    gemm_mma<true ><<<tcg, 256, SMEM_MMA>>>(Ahi, Alo, W1hi, W1lo, b1,
                                            nullptr, nullptr, Hhi, Hlo);
    gemm_mma<false><<<tcg, 256, SMEM_MMA>>>(Hhi, Hlo, W2hi, W2lo, b2,
                                            F + SZ, nullptr, nullptr, nullptr);

    for (int k = 2; k < MAXIT; ++k) {
        const int nv   = (k < MHIST) ? k : MHIST;
        const int slot = k % MHIST;
        launch_anderson_mix(nv, slot);   // -> z, X[slot], A split
        if (k < MAXIT - 1) {
            gemm_mma<true ><<<tcg, 256, SMEM_MMA>>>(Ahi, Alo, W1hi, W1lo, b1,
                                                    nullptr, nullptr, Hhi, Hlo);
            gemm_mma<false><<<tcg, 256, SMEM_MMA>>>(Hhi, Hlo, W2hi, W2lo, b2,
                                                    F + (size_t)slot * SZ,
                                                    nullptr, nullptr, nullptr);
        }
    }

    // out = z_star @ W_out + b_out (exact fp32)
    gemm_kernel<false><<<dim3(DOUT / 64, BATCH / 128), 256>>>(
        z, W_out, b_out, out, nullptr, nullptr, DOUT, DH);
}